// round 14
// baseline (speedup 1.0000x reference)
#include <cuda_runtime.h>

#define BB 32
#define HB 16                // batches per half
#define LL 64
#define NPAIRS 2016          // L*(L-1)/2
#define PPB 8                // pairs per block (one per warp)
#define PBLKS 252            // NPAIRS / PPB
#define NHALF 2

// pair p -> (l0<<6)|l1, constexpr-baked
struct T2Tab { int v[NPAIRS]; };
__host__ __device__ constexpr T2Tab make_t2() {
    T2Tab t{};
    int p = 0;
    for (int l1 = 1; l1 < 64; ++l1)
        for (int l0 = 0; l0 < l1; ++l0)
            t.v[p++] = (l0 << 6) | l1;
    return t;
}
__device__ constexpr T2Tab g_t2 = make_t2();

// cross-block scratch (zero at module load; kernel self-resets each call)
__device__ float    g_acc[BB];
__device__ unsigned g_cnt[NHALF];

__global__ void __launch_bounds__(256) gp_kernel(
        const float* __restrict__ x,
        const float* __restrict__ th0,
        const float* __restrict__ th1,
        const float* __restrict__ th2,
        const float* __restrict__ th3,
        float* __restrict__ out) {
    const int pairblk = blockIdx.x >> 1;     // [0,252)
    const int bh      = blockIdx.x & 1;      // batch half
    const int tid     = threadIdx.x;
    const int warp    = tid >> 5;
    const int lane    = tid & 31;

    __shared__ int   so_s[HB][LL];   // one-hot offsets o = l*4+c, 16 batches
    __shared__ float wsum[PPB][HB];
    __shared__ float o01[HB];        // order-0/1 per batch (block 0 only)

    // build so table for this half's 16 batches (1024 entries, 4 per thread)
    #pragma unroll
    for (int k = 0; k < 4; k++) {
        int idx = tid + 256 * k;             // [0,1024)
        int j = idx >> 6, pos = idx & 63;
        float4 v = ((const float4*)x)[(bh * HB + j) * LL + pos];
        int c = v.y > 0.5f ? 1 : (v.z > 0.5f ? 2 : (v.w > 0.5f ? 3 : 0));
        so_s[j][pos] = pos * 4 + c;
    }
    __syncthreads();

    // order 0 + 1 (block 0 only): warp w handles batches w and w+8
    if (pairblk == 0) {
        #pragma unroll
        for (int jj = 0; jj < 2; jj++) {
            int j = warp + jj * 8;
            float s = th1[so_s[j][lane]] + th1[so_s[j][lane + 32]];
            #pragma unroll
            for (int off = 16; off > 0; off >>= 1)
                s += __shfl_xor_sync(0xffffffffu, s, off);
            if (lane == 0) o01[j] = s + th0[0];
        }
    }

    // ---- this warp's pair ----
    const int pk = g_t2.v[pairblk * PPB + warp];
    const int l0 = pk >> 6;
    const int l1 = pk & 63;
    const int l2a = l1 + 1 + lane;
    const bool va = (l2a < LL);
    const bool vb = (l2a + 32 < LL);

    // 16 batches, fully unrolled: all load groups independent -> high MLP,
    // same-row repeats across batches hit L1.
    float acc[HB];
    #pragma unroll
    for (int j = 0; j < HB; j++) {
        const int o0 = so_s[j][l0];
        const int o1 = so_s[j][l1];
        const int base2 = o0 * 256 + o1;
        const float* __restrict__ row = th3 + (size_t)base2 * 256;
        float a = (lane == 0) ? th2[base2] : 0.f;   // order-2 term
        if (va) a += row[so_s[j][l2a]];
        if (vb) a += row[so_s[j][l2a + 32]];
        acc[j] = a;
    }

    // per-batch lane reduction, then per-warp partials to smem
    #pragma unroll
    for (int j = 0; j < HB; j++) {
        float a = acc[j];
        #pragma unroll
        for (int off = 16; off > 0; off >>= 1)
            a += __shfl_xor_sync(0xffffffffu, a, off);
        if (lane == 0) wsum[warp][j] = a;
    }
    __syncthreads();

    // 16 threads: merge 8 warps (+order-0/1 in block 0), atomicAdd global
    if (tid < HB) {
        float s = (pairblk == 0) ? o01[tid] : 0.f;
        #pragma unroll
        for (int w = 0; w < PPB; w++) s += wsum[w][tid];
        atomicAdd(&g_acc[bh * HB + tid], s);
        __threadfence();
    }
    __syncthreads();

    // last block of this half finalizes its 16 outputs
    if (tid == 0) {
        unsigned done = atomicAdd(&g_cnt[bh], 1u);
        if (done == PBLKS - 1) {
            __threadfence();
            #pragma unroll
            for (int j = 0; j < HB; j++) {
                int b = bh * HB + j;
                out[b] = g_acc[b];
                g_acc[b] = 0.f;      // reset for next replay
            }
            g_cnt[bh] = 0u;
        }
    }
}

extern "C" void kernel_launch(void* const* d_in, const int* in_sizes, int n_in,
                              void* d_out, int out_size) {
    const float* x   = (const float*)d_in[0];   // (B, L*C) one-hot
    const float* th0 = (const float*)d_in[1];   // (1,)
    const float* th1 = (const float*)d_in[2];   // (L, C)
    const float* th2 = (const float*)d_in[3];   // (L*C, L*C)
    const float* th3 = (const float*)d_in[4];   // (L*C, L*C, L*C)
    float* out = (float*)d_out;                 // (B, 1)

    gp_kernel<<<PBLKS * NHALF, 256>>>(x, th0, th1, th2, th3, out);
}

// round 15
// speedup vs baseline: 1.3145x; 1.3145x over previous
#include <cuda_runtime.h>

#define BB 32
#define LL 64
#define NPAIRS 2016          // L*(L-1)/2
#define WPB 16               // warps per block
#define NBLK 252             // 2016*2 halves / 16 warps
#define SOS 33               // padded stride for so_t (bank-conflict-free)

// pair p -> (l0<<6)|l1, constexpr-baked
struct T2Tab { int v[NPAIRS]; };
__host__ __device__ constexpr T2Tab make_t2() {
    T2Tab t{};
    int p = 0;
    for (int l1 = 1; l1 < 64; ++l1)
        for (int l0 = 0; l0 < l1; ++l0)
            t.v[p++] = (l0 << 6) | l1;
    return t;
}
__device__ constexpr T2Tab g_t2 = make_t2();

// cross-block scratch (zero at module load; kernel self-resets each call)
__device__ float    g_acc[BB];
__device__ unsigned g_cnt;

__global__ void __launch_bounds__(512) gp_kernel(
        const float* __restrict__ x,
        const float* __restrict__ th0,
        const float* __restrict__ th1,
        const float* __restrict__ th2,
        const float* __restrict__ th3,
        float* __restrict__ out) {
    const int k    = blockIdx.x;         // [0,252)
    const int tid  = threadIdx.x;
    const int warp = tid >> 5;           // [0,16)
    const int lane = tid & 31;           // lane == batch
    const int s    = warp >> 1;          // pair-slot [0,8)
    const int h    = warp & 1;           // l2-half
    const int p    = s * 252 + k;        // strided pair assignment (balance)

    __shared__ int   so_t[LL * SOS];     // so_t[pos*33 + b] = pos*4 + c
    __shared__ float wsum[WPB][32];
    __shared__ unsigned sflag;

    // fill transposed offset table: 2048 entries, coalesced x reads
    #pragma unroll
    for (int r = 0; r < 4; r++) {
        int idx = tid + 512 * r;         // [0,2048)
        int b   = idx >> 6;
        int pos = idx & 63;
        float4 v = ((const float4*)x)[b * LL + pos];
        int c = v.y > 0.5f ? 1 : (v.z > 0.5f ? 2 : (v.w > 0.5f ? 3 : 0));
        so_t[pos * SOS + b] = pos * 4 + c;
    }
    __syncthreads();

    // ---- this warp: pair p, half h, lane = batch ----
    const int pk = g_t2.v[p];
    const int l0 = pk >> 6;
    const int l1 = pk & 63;

    const int o0 = so_t[l0 * SOS + lane];
    const int o1 = so_t[l1 * SOS + lane];
    const int base2 = o0 * 256 + o1;
    const float* __restrict__ row = th3 + (size_t)base2 * 256;

    // order-2 term once per (pair, batch): half-0 warp only
    float acc = (h == 0) ? th2[base2] : 0.f;

    // strip over l2 (step 2 per half); iterations independent -> pipelined
    for (int l2 = l1 + 1 + h; l2 < LL; l2 += 2)
        acc += row[so_t[l2 * SOS + lane]];

    wsum[warp][lane] = acc;
    __syncthreads();

    // merge 16 warps per batch; block 0 also adds order 0+1
    if (tid < 32) {
        float t = 0.f;
        #pragma unroll
        for (int w = 0; w < WPB; w++) t += wsum[w][tid];
        if (k == 0) {
            float s1 = th0[0];
            #pragma unroll 8
            for (int l = 0; l < LL; l++) s1 += th1[so_t[l * SOS + tid]];
            t += s1;
        }
        atomicAdd(&g_acc[tid], t);
        __threadfence();
    }
    __syncthreads();

    // last block finalizes all 32 outputs
    if (tid == 0)
        sflag = (atomicAdd(&g_cnt, 1u) == NBLK - 1) ? 1u : 0u;
    __syncthreads();
    if (sflag) {
        __threadfence();
        if (tid < 32) {
            out[tid] = g_acc[tid];
            g_acc[tid] = 0.f;            // reset for next replay
        }
        if (tid == 0) g_cnt = 0u;
    }
}

extern "C" void kernel_launch(void* const* d_in, const int* in_sizes, int n_in,
                              void* d_out, int out_size) {
    const float* x   = (const float*)d_in[0];   // (B, L*C) one-hot
    const float* th0 = (const float*)d_in[1];   // (1,)
    const float* th1 = (const float*)d_in[2];   // (L, C)
    const float* th2 = (const float*)d_in[3];   // (L*C, L*C)
    const float* th3 = (const float*)d_in[4];   // (L*C, L*C, L*C)
    float* out = (float*)d_out;                 // (B, 1)

    gp_kernel<<<NBLK, 512>>>(x, th0, th1, th2, th3, out);
}